// round 8
// baseline (speedup 1.0000x reference)
#include <cuda_runtime.h>
#include <cuda_bf16.h>
#include <math.h>
#include <stdint.h>

// Problem constants
#define B       32
#define D       1024
#define VOCAB   50257
#define SEQ     128

// GEMM2 tiling (mma.sync m16n8k8 tf32; A = W1 (M=vocab), B = h (N=batch))
#define VBLK    384                        // vocab cols per CTA
#define NBLK    131                        // ceil(50257/384)
#define LSS     385                        // logits smem stride (padded)
#define GT      256                        // threads (8 warps)
#define SK      16                         // k rows per stage
#define NSTG    (D / SK)                   // 64 stages
#define DEPTH   3                          // cp.async pipeline depth
#define ROWP    392                        // padded W1 smem row (floats), ≡8 mod 32
#define CPR     97                         // 16B chunks per W1 row
#define HPITCH  1028                       // padded h smem row (floats), ≡4 mod 32
#define HBYTES  (B * HPITCH * 4)           // 131584
#define BSTAGE  (SK * ROWP * 4)            // 25088
#define SMEM_DYN (HBYTES + DEPTH * BSTAGE) // 206848 < 227KB

// GEMM1 k-split
#define KSPLIT  16

typedef unsigned long long ull;

// ---------------- device scratch ----------------
__device__ __align__(16) float g_h[B * D];     // h, tf32-rounded, row-major
__device__ float g_part[KSPLIT * B * D];
__device__ float g_pmax[NBLK * B];
__device__ float g_psum[NBLK * B];
__device__ float g_pg[NBLK];
__device__ int   g_lab64;
__device__ int   g_ctr;

// ---------------- helpers ----------------
__device__ __forceinline__ void ffma2(ull &acc, ull a, ull b) {
    asm("fma.rn.f32x2 %0, %1, %2, %0;" : "+l"(acc) : "l"(a), "l"(b));
}
__device__ __forceinline__ ull pack2(float w) {
    ull r; asm("mov.b64 %0, {%1, %1};" : "=l"(r) : "f"(w)); return r;
}
__device__ __forceinline__ void unpack2(ull v, float &lo, float &hi) {
    asm("mov.b64 {%0, %1}, %2;" : "=f"(lo), "=f"(hi) : "l"(v));
}
__device__ __forceinline__ uint32_t smem_u32(const void* p) {
    uint32_t a;
    asm("{ .reg .u64 t; cvta.to.shared.u64 t, %1; cvt.u32.u64 %0, t; }"
        : "=r"(a) : "l"(p));
    return a;
}
__device__ __forceinline__ uint32_t cvt_tf32(float f) {
    uint32_t r; asm("cvt.rna.tf32.f32 %0, %1;" : "=r"(r) : "f"(f)); return r;
}
__device__ __forceinline__ float lds_f(uint32_t a) {
    float v; asm volatile("ld.shared.f32 %0, [%1];" : "=f"(v) : "r"(a)); return v;
}
__device__ __forceinline__ void mma_tf32(float d[4], const uint32_t a[4],
                                         uint32_t b0, uint32_t b1) {
    asm volatile(
        "mma.sync.aligned.m16n8k8.row.col.f32.tf32.tf32.f32 "
        "{%0,%1,%2,%3}, {%4,%5,%6,%7}, {%8,%9}, {%0,%1,%2,%3};"
        : "+f"(d[0]), "+f"(d[1]), "+f"(d[2]), "+f"(d[3])
        : "r"(a[0]), "r"(a[1]), "r"(a[2]), "r"(a[3]), "r"(b0), "r"(b1));
}
__device__ __forceinline__ void cp16(uint32_t dst, const void* src) {
    asm volatile("cp.async.cg.shared.global [%0], [%1], 16;"
                 :: "r"(dst), "l"(src));
}

// ================= GEMM1 stage 1 (unchanged, proven) ======================
__global__ __launch_bounds__(256, 4) void g1_stage1(
    const float* __restrict__ z, const float* __restrict__ W0)
{
    __shared__ __align__(16) float zs[64 * 34];
    const int jt = blockIdx.x & 31;
    const int ks = blockIdx.x >> 5;
    const int j0 = jt * 32;
    const int k0 = ks * 64;
    const int t  = threadIdx.x;

    for (int i = t; i < B * 64; i += 256) {
        int bb = i >> 6, kk = i & 63;
        zs[kk * 34 + bb] = z[bb * D + k0 + kk];
    }
    __syncthreads();

    const int lane = t & 31;
    const int grp  = t >> 5;
    const int j    = j0 + lane;
    const int b0   = grp * 4;

    ull a0 = 0ull, a1 = 0ull;
    const ull* zs64 = (const ull*)zs;
    const float* pw = W0 + (size_t)k0 * D + j;

    #pragma unroll 16
    for (int kk = 0; kk < 64; ++kk) {
        float w = pw[kk * D];
        ull w2 = pack2(w);
        ull h0 = zs64[kk * 17 + (b0 >> 1)];
        ull h1 = zs64[kk * 17 + (b0 >> 1) + 1];
        ffma2(a0, h0, w2);
        ffma2(a1, h1, w2);
    }
    float f0, f1, f2, f3;
    unpack2(a0, f0, f1);
    unpack2(a1, f2, f3);
    float* dst = g_part + (size_t)ks * (B * D) + b0 * D + j;
    dst[0]      = f0;
    dst[D]      = f1;
    dst[2 * D]  = f2;
    dst[3 * D]  = f3;
}

// ===== GEMM1 stage 2: reduce + GELU -> tf32-rounded h (+ label probe) =====
__global__ void g1_stage2(const float* __restrict__ b0v,
                          const long long* __restrict__ labels)
{
    if (blockIdx.x == 0) {
        __shared__ int bad;
        if (threadIdx.x == 0) bad = 0;
        __syncthreads();
        for (int i = threadIdx.x; i < 2048; i += 256) {
            long long v = labels[i];
            if (v < 0 || v >= (long long)VOCAB) bad = 1;
        }
        __syncthreads();
        if (threadIdx.x == 0) g_lab64 = bad ? 0 : 1;
    }

    int idx = blockIdx.x * 256 + threadIdx.x;   // 0..32767
    int bb = idx >> 10;
    int j  = idx & 1023;
    float s = b0v[j];
    #pragma unroll
    for (int ks = 0; ks < KSPLIT; ++ks)
        s += g_part[(size_t)ks * (B * D) + bb * D + j];
    float gel = 0.5f * s * (1.0f + erff(s * 0.70710678118654752f));
    g_h[bb * D + j] = __uint_as_float(cvt_tf32(gel));
}

// ========== GEMM2: mma.sync tf32 (A=W1, B=h) + softmax + finalize =========
// W1 row k is 4B-aligned only; since VOCAB % 4 == 1 the misalignment of
// (k*VOCAB + vbase) is (k + vbase) & 3. cp.async 16B from the aligned-down
// address into a 392-float padded row; add the shift at fragment-read time.
__device__ __forceinline__ void load_bstage(uint32_t bsm, int buf, int s,
                                            const float* __restrict__ W1,
                                            int vbase, int t)
{
    const uint32_t sb = bsm + (uint32_t)buf * BSTAGE;
    const long maxe = (long)D * VOCAB - 4;
    for (int i = t; i < SK * CPR; i += GT) {
        int r = i / CPR, c = i - r * CPR;
        long e0 = (((long)(s * SK + r) * VOCAB + vbase) & ~3L) + (long)c * 4;
        if (e0 > maxe) e0 = maxe;
        cp16(sb + (uint32_t)(r * ROWP + c * 4) * 4, W1 + e0);
    }
}

__global__ __launch_bounds__(GT, 1) void gemm2_kernel(
    const float* __restrict__ W1, const float* __restrict__ b1,
    const void* __restrict__ labels, float* __restrict__ out)
{
    extern __shared__ __align__(1024) char dyn[];
    __shared__ float red[GT];
    __shared__ int   is_last;
    __shared__ float s_lse[B];

    const int t    = threadIdx.x;
    const int wid  = t >> 5, lane = t & 31;
    const int g    = lane >> 2;          // groupID
    const int tig  = lane & 3;           // thread-in-group
    const int vbase = blockIdx.x * VBLK;
    const uint32_t hsm = smem_u32(dyn);
    const uint32_t bsm = hsm + HBYTES;

    // prologue: h (pre-tf32) + W1 stages 0..2
    for (int i = t; i < B * (D / 4); i += GT) {         // 8192 16B chunks
        int bb = i >> 8, c = i & 255;
        cp16(hsm + (uint32_t)(bb * HPITCH + c * 4) * 4, g_h + bb * D + c * 4);
    }
    load_bstage(bsm, 0, 0, W1, vbase, t);
    asm volatile("cp.async.commit_group;" ::: "memory");
    load_bstage(bsm, 1, 1, W1, vbase, t);
    asm volatile("cp.async.commit_group;" ::: "memory");
    load_bstage(bsm, 2, 2, W1, vbase, t);
    asm volatile("cp.async.commit_group;" ::: "memory");

    // acc[mt][nt][4]: mt = 3 vocab m-tiles of 16, nt = 4 batch n-tiles of 8
    float acc[3][4][4];
    #pragma unroll
    for (int mt = 0; mt < 3; ++mt)
        #pragma unroll
        for (int nt = 0; nt < 4; ++nt)
            #pragma unroll
            for (int r = 0; r < 4; ++r) acc[mt][nt][r] = 0.f;

    const int n0w = wid * 48;            // warp's vocab base within block

    for (int s = 0; s < NSTG; ++s) {
        asm volatile("cp.async.wait_group 2;" ::: "memory");
        __syncthreads();
        const int buf = s % DEPTH;
        const uint32_t sb = bsm + (uint32_t)buf * BSTAGE;

        #pragma unroll
        for (int kb = 0; kb < SK; kb += 8) {
            const int kabs = s * SK + kb;
            // A fragments from W1 smem [k][n]: lane n-stride = 1 (no conflicts)
            const int sh = (kabs + tig + vbase) & 3;   // same for k and k+4
            const uint32_t r0 = sb + (uint32_t)((kb + tig)     * ROWP + sh) * 4;
            const uint32_t r1 = sb + (uint32_t)((kb + tig + 4) * ROWP + sh) * 4;
            uint32_t a[3][4];
            #pragma unroll
            for (int mt = 0; mt < 3; ++mt) {
                const uint32_t co = (uint32_t)(n0w + mt * 16 + g) * 4;
                a[mt][0] = cvt_tf32(lds_f(r0 + co));
                a[mt][1] = cvt_tf32(lds_f(r0 + co + 32));   // vocab +8
                a[mt][2] = cvt_tf32(lds_f(r1 + co));
                a[mt][3] = cvt_tf32(lds_f(r1 + co + 32));
            }
            // B fragments from h smem [b][k]: banks 4g+tig (conflict-free)
            uint32_t b0f[4], b1f[4];
            #pragma unroll
            for (int nt = 0; nt < 4; ++nt) {
                const uint32_t hr = hsm +
                    (uint32_t)((nt * 8 + g) * HPITCH + kabs + tig) * 4;
                b0f[nt] = __float_as_uint(lds_f(hr));
                b1f[nt] = __float_as_uint(lds_f(hr + 16));  // k +4
            }
            #pragma unroll
            for (int mt = 0; mt < 3; ++mt)
                #pragma unroll
                for (int nt = 0; nt < 4; ++nt)
                    mma_tf32(acc[mt][nt], a[mt], b0f[nt], b1f[nt]);
        }
        __syncthreads();
        if (s + DEPTH < NSTG)
            load_bstage(bsm, buf, s + DEPTH, W1, vbase, t);
        asm volatile("cp.async.commit_group;" ::: "memory");
    }
    asm volatile("cp.async.wait_group 0;" ::: "memory");
    __syncthreads();

    // ---- epilogue: fragments -> smem logits (+bias on vocab, tail mask) ---
    // Fragment (mt,nt): rows = vocab (g, g+8), cols = batch (2tig, 2tig+1).
    float* Ls = (float*)dyn;                      // [32][LSS]
    #pragma unroll
    for (int mt = 0; mt < 3; ++mt) {
        const int vloc0 = n0w + mt * 16 + g;
        const int v0 = vbase + vloc0, v8 = v0 + 8;
        const float bi0 = b1[v0 < VOCAB ? v0 : (VOCAB - 1)];
        const float bi8 = b1[v8 < VOCAB ? v8 : (VOCAB - 1)];
        #pragma unroll
        for (int nt = 0; nt < 4; ++nt) {
            const int bb = nt * 8 + 2 * tig;
            Ls[bb * LSS + vloc0]           = (v0 < VOCAB) ? acc[mt][nt][0] + bi0 : -1e30f;
            Ls[(bb + 1) * LSS + vloc0]     = (v0 < VOCAB) ? acc[mt][nt][1] + bi0 : -1e30f;
            Ls[bb * LSS + vloc0 + 8]       = (v8 < VOCAB) ? acc[mt][nt][2] + bi8 : -1e30f;
            Ls[(bb + 1) * LSS + vloc0 + 8] = (v8 < VOCAB) ? acc[mt][nt][3] + bi8 : -1e30f;
        }
    }
    __syncthreads();

    // ---- label gather ----
    const int lab64 = g_lab64;
    const long long* lab_ll = (const long long*)labels;
    const int*       lab_i  = (const int*)labels;
    float gg = 0.f;
    for (int i = t; i < B * SEQ; i += GT) {
        int bb = i >> 7;
        int lab = lab64 ? (int)lab_ll[i] : lab_i[i];
        int rel = lab - vbase;
        if (rel >= 0 && rel < VBLK) gg += Ls[bb * LSS + rel];
    }
    red[t] = gg;
    __syncthreads();
    for (int off = GT / 2; off; off >>= 1) {
        if (t < off) red[t] += red[t + off];
        __syncthreads();
    }
    if (t == 0) g_pg[blockIdx.x] = red[0];

    // ---- per-b partial (max, sumexp) over this block's 384 cols ----
    #pragma unroll
    for (int bi = 0; bi < 4; ++bi) {
        const int bb = wid * 4 + bi;
        float m = -1e30f;
        for (int vv = lane; vv < VBLK; vv += 32)
            m = fmaxf(m, Ls[bb * LSS + vv]);
        #pragma unroll
        for (int o = 16; o; o >>= 1)
            m = fmaxf(m, __shfl_xor_sync(0xffffffffu, m, o));
        float sum = 0.f;
        for (int vv = lane; vv < VBLK; vv += 32)
            sum += __expf(Ls[bb * LSS + vv] - m);
        #pragma unroll
        for (int o = 16; o; o >>= 1)
            sum += __shfl_xor_sync(0xffffffffu, sum, o);
        if (lane == 0) {
            g_pmax[blockIdx.x * B + bb] = m;
            g_psum[blockIdx.x * B + bb] = sum;
        }
    }

    // ---- fused finalize: last block reduces all partials ----
    __threadfence();
    __syncthreads();
    if (t == 0) {
        int old = atomicAdd(&g_ctr, 1);
        is_last = (old == NBLK - 1);
    }
    __syncthreads();
    if (!is_last) return;
    __threadfence();

    #pragma unroll
    for (int bi = 0; bi < 4; ++bi) {
        const int bb = wid * 4 + bi;
        float m = -1e30f;
        for (int i = lane; i < NBLK; i += 32)
            m = fmaxf(m, g_pmax[i * B + bb]);
        #pragma unroll
        for (int o = 16; o; o >>= 1)
            m = fmaxf(m, __shfl_xor_sync(0xffffffffu, m, o));
        float sum = 0.f;
        for (int i = lane; i < NBLK; i += 32)
            sum += g_psum[i * B + bb] * __expf(g_pmax[i * B + bb] - m);
        #pragma unroll
        for (int o = 16; o; o >>= 1)
            sum += __shfl_xor_sync(0xffffffffu, sum, o);
        if (lane == 0) s_lse[bb] = m + logf(sum);
    }
    red[t] = (t < NBLK) ? g_pg[t] : 0.f;
    __syncthreads();
    for (int off = GT / 2; off; off >>= 1) {
        if (t < off) red[t] += red[t + off];
        __syncthreads();
    }
    if (t == 0) {
        float L = 0.f;
        #pragma unroll
        for (int bb = 0; bb < B; ++bb) L += s_lse[bb];
        out[0] = L / (float)B - red[0] / (float)(B * SEQ);
        g_ctr = 0;
    }
}

// =========================== launch ======================================
extern "C" void kernel_launch(void* const* d_in, const int* in_sizes, int n_in,
                              void* d_out, int out_size)
{
    const float* z = nullptr; const void* labels = nullptr;
    const float* W0 = nullptr; const float* b0 = nullptr;
    const float* W1 = nullptr; const float* b1 = nullptr;
    for (int i = 0; i < n_in; ++i) {
        switch (in_sizes[i]) {
            case B * D:        z      = (const float*)d_in[i];      break;
            case B * SEQ:      labels = d_in[i];                    break;
            case D * D:        W0     = (const float*)d_in[i];      break;
            case D:            b0     = (const float*)d_in[i];      break;
            case D * VOCAB:    W1     = (const float*)d_in[i];      break;
            case VOCAB:        b1     = (const float*)d_in[i];      break;
            default: break;
        }
    }

    static bool attr_done = false;
    if (!attr_done) {
        cudaFuncSetAttribute(gemm2_kernel,
                             cudaFuncAttributeMaxDynamicSharedMemorySize,
                             SMEM_DYN);
        attr_done = true;
    }

    g1_stage1<<<512, 256>>>(z, W0);
    g1_stage2<<<128, 256>>>(b0, (const long long*)labels);
    gemm2_kernel<<<NBLK, GT, SMEM_DYN>>>(W1, b1, labels, (float*)d_out);
}